// round 8
// baseline (speedup 1.0000x reference)
#include <cuda_runtime.h>
#include <cuda_bf16.h>
#include <cstdint>

// Problem constants: N=100000, E=800000, D=128, H=4, DH=32
#define MAX_N 100096
#define ND ((size_t)MAX_N * 128)

__device__ float g_Q[ND];
__device__ float g_K[ND];
__device__ float g_V[ND];
__device__ __nv_bfloat16 g_Yhi[ND], g_Ylo[ND];
__device__ __nv_bfloat16 g_Whi[4 * 16384], g_Wlo[4 * 16384];  // Wq,Wk,Wv,Wo(K-permuted)
__device__ int g_rowptr[MAX_N + 1];

#define LDROW 136      // bf16 elems per padded smem row (conflict-free ldmatrix)
#define A_ROWS 32

// qkv smem layout (bf16 elems): A hi | A lo | B hi | B lo   (single A buffer)
#define QKV_A_PART (A_ROWS * LDROW)              // 4352
#define QKV_B_HI   (2 * QKV_A_PART)              // 8704
#define QKV_B_LO   (QKV_B_HI + 128 * LDROW)
#define QKV_SMEM_BYTES ((QKV_B_LO + 128 * LDROW) * 2)   // 87040

// out smem layout: A double-buffered hi/lo | B hi | B lo
#define OUT_A_PART (A_ROWS * LDROW)
#define OUT_A_BUF  (2 * OUT_A_PART)
#define OUT_B_HI   (2 * OUT_A_BUF)
#define OUT_B_LO   (OUT_B_HI + 128 * LDROW)
#define OUT_SMEM_BYTES ((OUT_B_LO + 128 * LDROW) * 2)   // 104448

// ---------------------------------------------------------------------------
__device__ __forceinline__ uint32_t smem_u32(const void* p) {
    uint32_t a;
    asm("{ .reg .u64 t; cvta.to.shared.u64 t, %1; cvt.u32.u64 %0, t; }" : "=r"(a) : "l"(p));
    return a;
}
__device__ __forceinline__ void ldm_x4(uint32_t* r, uint32_t addr) {
    asm volatile("ldmatrix.sync.aligned.m8n8.x4.shared.b16 {%0,%1,%2,%3}, [%4];"
                 : "=r"(r[0]), "=r"(r[1]), "=r"(r[2]), "=r"(r[3]) : "r"(addr));
}
__device__ __forceinline__ void mma16816(float* d, const uint32_t* a, const uint32_t* b) {
    asm volatile(
        "mma.sync.aligned.m16n8k16.row.col.f32.bf16.bf16.f32 "
        "{%0,%1,%2,%3},{%4,%5,%6,%7},{%8,%9},{%0,%1,%2,%3};"
        : "+f"(d[0]), "+f"(d[1]), "+f"(d[2]), "+f"(d[3])
        : "r"(a[0]), "r"(a[1]), "r"(a[2]), "r"(a[3]), "r"(b[0]), "r"(b[1]));
}
__device__ __forceinline__ void cp16(uint32_t saddr, const void* gptr) {
    asm volatile("cp.async.ca.shared.global [%0], [%1], 16;" :: "r"(saddr), "l"(gptr));
}
#define CP_COMMIT() asm volatile("cp.async.commit_group;" ::: "memory")
#define CP_WAIT0()  asm volatile("cp.async.wait_group 0;" ::: "memory")

__device__ __forceinline__ void split4(float4 v, __nv_bfloat162* hi0, __nv_bfloat162* hi1,
                                       __nv_bfloat162* lo0, __nv_bfloat162* lo1) {
    __nv_bfloat16 h0 = __float2bfloat16_rn(v.x), h1 = __float2bfloat16_rn(v.y);
    __nv_bfloat16 h2 = __float2bfloat16_rn(v.z), h3 = __float2bfloat16_rn(v.w);
    hi0->x = h0; hi0->y = h1; hi1->x = h2; hi1->y = h3;
    lo0->x = __float2bfloat16_rn(v.x - __bfloat162float(h0));
    lo0->y = __float2bfloat16_rn(v.y - __bfloat162float(h1));
    lo1->x = __float2bfloat16_rn(v.z - __bfloat162float(h2));
    lo1->y = __float2bfloat16_rn(v.w - __bfloat162float(h3));
}

// ---------------------------------------------------------------------------
// Weight conversion only: {Wq,Wk,Wv,Wo(K-perm)} -> g_Whi/lo  (tiny kernel)
// ---------------------------------------------------------------------------
__global__ void convert_weights(const float* __restrict__ Wq, const float* __restrict__ Wk,
                                const float* __restrict__ Wv, const float* __restrict__ Wo)
{
    const int idx = blockIdx.x * blockDim.x + threadIdx.x;
    if (idx >= 4 * 16384) return;
    const int mat = idx >> 14, e = idx & 16383;
    const int f = e >> 7, k = e & 127;
    const float* W = (mat == 0) ? Wq : (mat == 1) ? Wk : (mat == 2) ? Wv : Wo;
    const int kk = (mat == 3) ? ((k & 31) * 4 + (k >> 5)) : k;  // undo head-major for Wo
    const float v = W[f * 128 + kk];
    __nv_bfloat16 h = __float2bfloat16_rn(v);
    g_Whi[idx] = h;
    g_Wlo[idx] = __float2bfloat16_rn(v - __bfloat162float(h));
}

// ---------------------------------------------------------------------------
// CSR rowptr from sorted row[]
// ---------------------------------------------------------------------------
__global__ void build_rowptr(const int* __restrict__ row, int E, int Nn)
{
    const int e = blockIdx.x * blockDim.x + threadIdx.x;
    if (e >= E) return;
    const int r = row[e];
    const int prev = (e == 0) ? -1 : row[e - 1];
    for (int j = prev + 1; j <= r; j++) g_rowptr[j] = e;
    if (e == E - 1)
        for (int j = r + 1; j <= Nn; j++) g_rowptr[j] = E;
}

// ---------------------------------------------------------------------------
// Warp-MMA tile: acc += Ahi*Bhi + Alo*Bhi + Ahi*Blo, K=128 resident.
// 8 warps: warp_m = w&1 (16 rows), warp_n = w>>1 (32 cols). Warp tile 16x32.
// ---------------------------------------------------------------------------
__device__ __forceinline__ void mma_tile(float acc[4][4],
                                         uint32_t AHI, uint32_t ALO,
                                         uint32_t BHI, uint32_t BLO,
                                         int warp_m, int warp_n, int lane)
{
    const uint32_t a_off = (uint32_t)((warp_m * 16 + (lane & 15)) * LDROW + ((lane >> 4) << 3)) * 2;
    const uint32_t b_off = (uint32_t)((warp_n * 32 + (lane & 7) + ((lane >> 4) << 3)) * LDROW +
                                      (lane & 8)) * 2;
    #pragma unroll
    for (int ks = 0; ks < 8; ks++) {
        const uint32_t kb = (uint32_t)ks * 32;   // 16 bf16 = 32 B
        uint32_t aH[4], aL[4], bH[2][4], bL[2][4];
        ldm_x4(aH, AHI + a_off + kb);
        #pragma unroll
        for (int g = 0; g < 2; g++)
            ldm_x4(bH[g], BHI + b_off + kb + (uint32_t)(g * 16 * LDROW) * 2);
        #pragma unroll
        for (int g = 0; g < 2; g++) {
            mma16816(acc[2 * g],     aH, bH[g]);
            mma16816(acc[2 * g + 1], aH, bH[g] + 2);
        }
        ldm_x4(aL, ALO + a_off + kb);
        #pragma unroll
        for (int g = 0; g < 2; g++) {
            mma16816(acc[2 * g],     aL, bH[g]);
            mma16816(acc[2 * g + 1], aL, bH[g] + 2);
        }
        #pragma unroll
        for (int g = 0; g < 2; g++)
            ldm_x4(bL[g], BLO + b_off + kb + (uint32_t)(g * 16 * LDROW) * 2);
        #pragma unroll
        for (int g = 0; g < 2; g++) {
            mma16816(acc[2 * g],     aH, bL[g]);
            mma16816(acc[2 * g + 1], aH, bL[g] + 2);
        }
    }
}

__device__ __forceinline__ void load_B_async(uint32_t sbase, uint32_t bhi_e, uint32_t blo_e,
                                             int tid,
                                             const __nv_bfloat16* Bhi, const __nv_bfloat16* Blo)
{
    #pragma unroll
    for (int c = 0; c < 2048; c += 256) {
        const int cc = c + tid;
        const int r = cc >> 4, col = (cc & 15) * 8;
        cp16(sbase + (bhi_e + (uint32_t)(r * LDROW + col)) * 2, Bhi + r * 128 + col);
        cp16(sbase + (blo_e + (uint32_t)(r * LDROW + col)) * 2, Blo + r * 128 + col);
    }
}

// ---------------------------------------------------------------------------
// Persistent QKV projection: loads fp32 x directly (register prefetch),
// converts to hi/lo smem in-register. grid=(99,3). Head-major outputs; Q*0.5.
// ---------------------------------------------------------------------------
__global__ __launch_bounds__(256, 2) void qkv_tc(
    const float* __restrict__ x,
    const float* __restrict__ bq, const float* __restrict__ bk,
    const float* __restrict__ bv, int Nn, int ntiles)
{
    extern __shared__ __nv_bfloat16 sm[];
    const uint32_t sbase = smem_u32(sm);
    const int tid = threadIdx.x;
    const int lane = tid & 31;
    const int w = tid >> 5;
    const int warp_m = w & 1;
    const int warp_n = w >> 1;
    const int o = blockIdx.y;

    float* dst = (o == 0) ? g_Q : (o == 1) ? g_K : g_V;
    const float alpha = (o == 0) ? 0.5f : 1.0f;
    const float* bias = (o == 0) ? bq : (o == 1) ? bk : bv;

    // hoisted epilogue constants (fixed per thread)
    int p0c[4], p1c[4];
    float b0c[4], b1c[4];
    #pragma unroll
    for (int nb = 0; nb < 4; nb++) {
        const int f0 = warp_n * 32 + nb * 8 + (lane & 3) * 2;
        const int f1 = f0 + 1;
        p0c[nb] = (f0 & 3) * 32 + (f0 >> 2);
        p1c[nb] = (f1 & 3) * 32 + (f1 >> 2);
        b0c[nb] = __ldg(&bias[f0]);
        b1c[nb] = __ldg(&bias[f1]);
    }

    load_B_async(sbase, QKV_B_HI, QKV_B_LO, tid, g_Whi + o * 16384, g_Wlo + o * 16384);
    CP_COMMIT();

    // A-loader mapping: 8 threads per row, 16 floats each
    const int arow = tid >> 3;
    const int acol = (tid & 7) * 16;

    int t = blockIdx.x;
    float4 r[4];
    if (t < ntiles) {
        const int m = t * A_ROWS + arow;
        const float* src = x + (size_t)m * 128 + acol;
        const bool v = m < Nn;
        #pragma unroll
        for (int i = 0; i < 4; i++)
            r[i] = v ? *(const float4*)(src + i * 4) : make_float4(0.f, 0.f, 0.f, 0.f);
    }
    CP_WAIT0();
    __syncthreads();   // B resident

    for (; t < ntiles; t += gridDim.x) {
        // convert prefetched regs -> A hi/lo smem
        #pragma unroll
        for (int i = 0; i < 4; i++) {
            const uint32_t e = (uint32_t)(arow * LDROW + acol + i * 4);
            split4(r[i],
                   (__nv_bfloat162*)&sm[e], (__nv_bfloat162*)&sm[e + 2],
                   (__nv_bfloat162*)&sm[QKV_A_PART + e], (__nv_bfloat162*)&sm[QKV_A_PART + e + 2]);
        }
        // prefetch next tile
        const int tn = t + gridDim.x;
        float4 rn[4];
        if (tn < ntiles) {
            const int m = tn * A_ROWS + arow;
            const float* src = x + (size_t)m * 128 + acol;
            const bool v = m < Nn;
            #pragma unroll
            for (int i = 0; i < 4; i++)
                rn[i] = v ? *(const float4*)(src + i * 4) : make_float4(0.f, 0.f, 0.f, 0.f);
        }
        __syncthreads();   // A hi/lo visible

        float acc[4][4];
        #pragma unroll
        for (int nb = 0; nb < 4; nb++)
            #pragma unroll
            for (int j = 0; j < 4; j++) acc[nb][j] = 0.f;

        mma_tile(acc, sbase, sbase + (uint32_t)QKV_A_PART * 2,
                 sbase + (uint32_t)QKV_B_HI * 2, sbase + (uint32_t)QKV_B_LO * 2,
                 warp_m, warp_n, lane);

        const int mrow = t * A_ROWS + warp_m * 16 + (lane >> 2);
        #pragma unroll
        for (int nb = 0; nb < 4; nb++) {
            if (mrow < Nn) {
                dst[(size_t)mrow * 128 + p0c[nb]] = (acc[nb][0] + b0c[nb]) * alpha;
                dst[(size_t)mrow * 128 + p1c[nb]] = (acc[nb][1] + b1c[nb]) * alpha;
            }
            if (mrow + 8 < Nn) {
                dst[(size_t)(mrow + 8) * 128 + p0c[nb]] = (acc[nb][2] + b0c[nb]) * alpha;
                dst[(size_t)(mrow + 8) * 128 + p1c[nb]] = (acc[nb][3] + b1c[nb]) * alpha;
            }
        }
        __syncthreads();   // all warps done with A before next convert
        #pragma unroll
        for (int i = 0; i < 4; i++) r[i] = rn[i];
    }
}

// ---------------------------------------------------------------------------
// Persistent output projection: A = Y hi/lo (bf16 from edge_attn), B = Wo.
// Double-buffered cp.async A tiles.
// ---------------------------------------------------------------------------
__device__ __forceinline__ void out_load_A(uint32_t sbase, int buf, int tid, int m0)
{
    const uint32_t abase = (uint32_t)(buf * OUT_A_BUF);
    #pragma unroll
    for (int c = 0; c < 512; c += 256) {
        const int cc = c + tid;
        const int r = cc >> 4, col = (cc & 15) * 8;
        cp16(sbase + (abase + (uint32_t)(r * LDROW + col)) * 2,
             g_Yhi + (size_t)(m0 + r) * 128 + col);
        cp16(sbase + (abase + (uint32_t)(OUT_A_PART + r * LDROW + col)) * 2,
             g_Ylo + (size_t)(m0 + r) * 128 + col);
    }
}

__global__ __launch_bounds__(256, 2) void out_tc(
    const float* __restrict__ bo, float* __restrict__ out, int Nn, int ntiles)
{
    extern __shared__ __nv_bfloat16 sm[];
    const uint32_t sbase = smem_u32(sm);
    const int tid = threadIdx.x;
    const int lane = tid & 31;
    const int w = tid >> 5;
    const int warp_m = w & 1;
    const int warp_n = w >> 1;

    float b0c[4], b1c[4];
    #pragma unroll
    for (int nb = 0; nb < 4; nb++) {
        const int f0 = warp_n * 32 + nb * 8 + (lane & 3) * 2;
        b0c[nb] = __ldg(&bo[f0]);
        b1c[nb] = __ldg(&bo[f0 + 1]);
    }

    load_B_async(sbase, OUT_B_HI, OUT_B_LO, tid, g_Whi + 3 * 16384, g_Wlo + 3 * 16384);
    int t = blockIdx.x;
    if (t < ntiles) out_load_A(sbase, 0, tid, t * A_ROWS);
    CP_COMMIT();

    int buf = 0;
    for (; t < ntiles; t += gridDim.x) {
        CP_WAIT0();
        __syncthreads();
        const int tn = t + gridDim.x;
        if (tn < ntiles) {
            out_load_A(sbase, buf ^ 1, tid, tn * A_ROWS);
            CP_COMMIT();
        }

        float acc[4][4];
        #pragma unroll
        for (int nb = 0; nb < 4; nb++)
            #pragma unroll
            for (int j = 0; j < 4; j++) acc[nb][j] = 0.f;

        const uint32_t AHI = sbase + (uint32_t)(buf * OUT_A_BUF) * 2;
        mma_tile(acc, AHI, AHI + (uint32_t)OUT_A_PART * 2,
                 sbase + (uint32_t)OUT_B_HI * 2, sbase + (uint32_t)OUT_B_LO * 2,
                 warp_m, warp_n, lane);

        const int mrow = t * A_ROWS + warp_m * 16 + (lane >> 2);
        #pragma unroll
        for (int nb = 0; nb < 4; nb++) {
            const int f0 = warp_n * 32 + nb * 8 + (lane & 3) * 2;
            if (mrow < Nn) {
                float2 v = make_float2(acc[nb][0] + b0c[nb], acc[nb][1] + b1c[nb]);
                *(float2*)&out[(size_t)mrow * 128 + f0] = v;
            }
            if (mrow + 8 < Nn) {
                float2 v = make_float2(acc[nb][2] + b0c[nb], acc[nb][3] + b1c[nb]);
                *(float2*)&out[(size_t)(mrow + 8) * 128 + f0] = v;
            }
        }
        buf ^= 1;
    }
}

// ---------------------------------------------------------------------------
// Fused edge attention (R6 version — at the memory roofline): one warp per
// node, rowptr lookup, no max-subtract, unroll-4 direct __ldg col loads.
// ---------------------------------------------------------------------------
__device__ __forceinline__ float head_dot(float4 a, float4 b) {
    float s = a.x * b.x + a.y * b.y + a.z * b.z + a.w * b.w;
    s += __shfl_xor_sync(0xffffffffu, s, 1);
    s += __shfl_xor_sync(0xffffffffu, s, 2);
    s += __shfl_xor_sync(0xffffffffu, s, 4);
    return s;
}

__global__ __launch_bounds__(256) void edge_attn(const int* __restrict__ col, int Nn)
{
    const int i = (blockIdx.x * blockDim.x + threadIdx.x) >> 5;
    const int lane = threadIdx.x & 31;
    if (i >= Nn) return;

    const int start = g_rowptr[i];
    const int end   = g_rowptr[i + 1];

    const float4 qv = *(const float4*)&g_Q[(size_t)i * 128 + lane * 4];

    float l = 0.f;
    float4 acc = make_float4(0.f, 0.f, 0.f, 0.f);

    int e = start;
    for (; e + 4 <= end; e += 4) {
        const int c0 = __ldg(&col[e]);
        const int c1 = __ldg(&col[e + 1]);
        const int c2 = __ldg(&col[e + 2]);
        const int c3 = __ldg(&col[e + 3]);
        const float4 k0 = *(const float4*)&g_K[(size_t)c0 * 128 + lane * 4];
        const float4 k1 = *(const float4*)&g_K[(size_t)c1 * 128 + lane * 4];
        const float4 k2 = *(const float4*)&g_K[(size_t)c2 * 128 + lane * 4];
        const float4 k3 = *(const float4*)&g_K[(size_t)c3 * 128 + lane * 4];
        const float4 v0 = *(const float4*)&g_V[(size_t)c0 * 128 + lane * 4];
        const float4 v1 = *(const float4*)&g_V[(size_t)c1 * 128 + lane * 4];
        const float4 v2 = *(const float4*)&g_V[(size_t)c2 * 128 + lane * 4];
        const float4 v3 = *(const float4*)&g_V[(size_t)c3 * 128 + lane * 4];

        float s0 = qv.x * k0.x + qv.y * k0.y + qv.z * k0.z + qv.w * k0.w;
        float s1 = qv.x * k1.x + qv.y * k1.y + qv.z * k1.z + qv.w * k1.w;
        float s2 = qv.x * k2.x + qv.y * k2.y + qv.z * k2.z + qv.w * k2.w;
        float s3 = qv.x * k3.x + qv.y * k3.y + qv.z * k3.z + qv.w * k3.w;
        s0 += __shfl_xor_sync(0xffffffffu, s0, 1);
        s1 += __shfl_xor_sync(0xffffffffu, s1, 1);
        s2 += __shfl_xor_sync(0xffffffffu, s2, 1);
        s3 += __shfl_xor_sync(0xffffffffu, s3, 1);
        s0 += __shfl_xor_sync(0xffffffffu, s0, 2);
        s1 += __shfl_xor_sync(0xffffffffu, s1, 2);
        s2 += __shfl_xor_sync(0xffffffffu, s2, 2);
        s3 += __shfl_xor_sync(0xffffffffu, s3, 2);
        s0 += __shfl_xor_sync(0xffffffffu, s0, 4);
        s1 += __shfl_xor_sync(0xffffffffu, s1, 4);
        s2 += __shfl_xor_sync(0xffffffffu, s2, 4);
        s3 += __shfl_xor_sync(0xffffffffu, s3, 4);

        const float w0 = __expf(s0);
        const float w1 = __expf(s1);
        const float w2 = __expf(s2);
        const float w3 = __expf(s3);
        l += (w0 + w1) + (w2 + w3);

        acc.x += w0 * v0.x + w1 * v1.x + w2 * v2.x + w3 * v3.x;
        acc.y += w0 * v0.y + w1 * v1.y + w2 * v2.y + w3 * v3.y;
        acc.z += w0 * v0.z + w1 * v1.z + w2 * v2.z + w3 * v3.z;
        acc.w += w0 * v0.w + w1 * v1.w + w2 * v2.w + w3 * v3.w;
    }
    for (; e < end; e++) {
        const int c = __ldg(&col[e]);
        const float4 kv = *(const float4*)&g_K[(size_t)c * 128 + lane * 4];
        const float4 vv = *(const float4*)&g_V[(size_t)c * 128 + lane * 4];
        const float wgt = __expf(head_dot(qv, kv));
        l += wgt;
        acc.x += wgt * vv.x;
        acc.y += wgt * vv.y;
        acc.z += wgt * vv.z;
        acc.w += wgt * vv.w;
    }

    const float inv = (l > 0.f) ? (1.f / l) : 0.f;
    float4 o;
    o.x = acc.x * inv; o.y = acc.y * inv; o.z = acc.z * inv; o.w = acc.w * inv;

    __nv_bfloat162 hp0, hp1, lp0, lp1;
    split4(o, &hp0, &hp1, &lp0, &lp1);
    const size_t base = (size_t)i * 128 + lane * 4;
    *(__nv_bfloat162*)&g_Yhi[base]     = hp0;
    *(__nv_bfloat162*)&g_Yhi[base + 2] = hp1;
    *(__nv_bfloat162*)&g_Ylo[base]     = lp0;
    *(__nv_bfloat162*)&g_Ylo[base + 2] = lp1;
}

// ---------------------------------------------------------------------------
extern "C" void kernel_launch(void* const* d_in, const int* in_sizes, int n_in,
                              void* d_out, int out_size)
{
    const float* x  = (const float*)d_in[0];
    const int*   row = (const int*)d_in[1];
    const int*   col = (const int*)d_in[2];
    const float* Wq = (const float*)d_in[3];
    const float* bq = (const float*)d_in[4];
    const float* Wk = (const float*)d_in[5];
    const float* bk = (const float*)d_in[6];
    const float* Wv = (const float*)d_in[7];
    const float* bv = (const float*)d_in[8];
    const float* Wo = (const float*)d_in[9];
    const float* bo = (const float*)d_in[10];

    const int Nn = in_sizes[0] / 128;
    const int E  = in_sizes[1];
    const int ntiles = (Nn + A_ROWS - 1) / A_ROWS;

    cudaFuncSetAttribute(qkv_tc, cudaFuncAttributeMaxDynamicSharedMemorySize, QKV_SMEM_BYTES);
    cudaFuncSetAttribute(out_tc, cudaFuncAttributeMaxDynamicSharedMemorySize, OUT_SMEM_BYTES);

    convert_weights<<<256, 256>>>(Wq, Wk, Wv, Wo);
    build_rowptr<<<(E + 255) / 256, 256>>>(row, E, Nn);

    qkv_tc<<<dim3(99, 3), 256, QKV_SMEM_BYTES>>>(x, bq, bk, bv, Nn, ntiles);

    const int edge_blocks = (Nn * 32 + 255) / 256;
    edge_attn<<<edge_blocks, 256>>>(col, Nn);

    out_tc<<<dim3(296, 1), 256, OUT_SMEM_BYTES>>>(bo, (float*)d_out, Nn, ntiles);
}

// round 9
// speedup vs baseline: 1.4526x; 1.4526x over previous
#include <cuda_runtime.h>
#include <cuda_bf16.h>
#include <cstdint>

// Problem constants: N=100000, E=800000, D=128, H=4, DH=32
#define MAX_N 100096
#define ND ((size_t)MAX_N * 128)

__device__ float g_Q[ND];
__device__ float g_KV[(size_t)MAX_N * 256];   // per node: K[0..127] | V[128..255]
__device__ __nv_bfloat16 g_Yhi[ND], g_Ylo[ND];
__device__ __nv_bfloat16 g_Whi[4 * 16384], g_Wlo[4 * 16384];  // Wq,Wk,Wv,Wo(K-permuted)
__device__ int g_rowptr[MAX_N + 1];

#define LDROW 136      // bf16 elems per padded smem row (conflict-free ldmatrix)
#define A_ROWS 32

// qkv smem layout (bf16 elems): A hi | A lo | B hi | B lo   (single A buffer)
#define QKV_A_PART (A_ROWS * LDROW)              // 4352
#define QKV_B_HI   (2 * QKV_A_PART)              // 8704
#define QKV_B_LO   (QKV_B_HI + 128 * LDROW)
#define QKV_SMEM_BYTES ((QKV_B_LO + 128 * LDROW) * 2)   // 87040

// out smem layout: A double-buffered hi/lo | B hi | B lo
#define OUT_A_PART (A_ROWS * LDROW)
#define OUT_A_BUF  (2 * OUT_A_PART)
#define OUT_B_HI   (2 * OUT_A_BUF)
#define OUT_B_LO   (OUT_B_HI + 128 * LDROW)
#define OUT_SMEM_BYTES ((OUT_B_LO + 128 * LDROW) * 2)   // 104448

// ---------------------------------------------------------------------------
__device__ __forceinline__ uint32_t smem_u32(const void* p) {
    uint32_t a;
    asm("{ .reg .u64 t; cvta.to.shared.u64 t, %1; cvt.u32.u64 %0, t; }" : "=r"(a) : "l"(p));
    return a;
}
__device__ __forceinline__ void ldm_x4(uint32_t* r, uint32_t addr) {
    asm volatile("ldmatrix.sync.aligned.m8n8.x4.shared.b16 {%0,%1,%2,%3}, [%4];"
                 : "=r"(r[0]), "=r"(r[1]), "=r"(r[2]), "=r"(r[3]) : "r"(addr));
}
__device__ __forceinline__ void mma16816(float* d, const uint32_t* a, const uint32_t* b) {
    asm volatile(
        "mma.sync.aligned.m16n8k16.row.col.f32.bf16.bf16.f32 "
        "{%0,%1,%2,%3},{%4,%5,%6,%7},{%8,%9},{%0,%1,%2,%3};"
        : "+f"(d[0]), "+f"(d[1]), "+f"(d[2]), "+f"(d[3])
        : "r"(a[0]), "r"(a[1]), "r"(a[2]), "r"(a[3]), "r"(b[0]), "r"(b[1]));
}
__device__ __forceinline__ void cp16(uint32_t saddr, const void* gptr) {
    asm volatile("cp.async.ca.shared.global [%0], [%1], 16;" :: "r"(saddr), "l"(gptr));
}
#define CP_COMMIT() asm volatile("cp.async.commit_group;" ::: "memory")
#define CP_WAIT0()  asm volatile("cp.async.wait_group 0;" ::: "memory")

__device__ __forceinline__ void split4(float4 v, __nv_bfloat162* hi0, __nv_bfloat162* hi1,
                                       __nv_bfloat162* lo0, __nv_bfloat162* lo1) {
    __nv_bfloat16 h0 = __float2bfloat16_rn(v.x), h1 = __float2bfloat16_rn(v.y);
    __nv_bfloat16 h2 = __float2bfloat16_rn(v.z), h3 = __float2bfloat16_rn(v.w);
    hi0->x = h0; hi0->y = h1; hi1->x = h2; hi1->y = h3;
    lo0->x = __float2bfloat16_rn(v.x - __bfloat162float(h0));
    lo0->y = __float2bfloat16_rn(v.y - __bfloat162float(h1));
    lo1->x = __float2bfloat16_rn(v.z - __bfloat162float(h2));
    lo1->y = __float2bfloat16_rn(v.w - __bfloat162float(h3));
}

// ---------------------------------------------------------------------------
// Weight conversion: {Wq,Wk,Wv,Wo(K-perm)} -> g_Whi/lo  (tiny kernel)
// ---------------------------------------------------------------------------
__global__ void convert_weights(const float* __restrict__ Wq, const float* __restrict__ Wk,
                                const float* __restrict__ Wv, const float* __restrict__ Wo)
{
    const int idx = blockIdx.x * blockDim.x + threadIdx.x;
    if (idx >= 4 * 16384) return;
    const int mat = idx >> 14, e = idx & 16383;
    const int f = e >> 7, k = e & 127;
    const float* W = (mat == 0) ? Wq : (mat == 1) ? Wk : (mat == 2) ? Wv : Wo;
    const int kk = (mat == 3) ? ((k & 31) * 4 + (k >> 5)) : k;  // undo head-major for Wo
    const float v = W[f * 128 + kk];
    __nv_bfloat16 h = __float2bfloat16_rn(v);
    g_Whi[idx] = h;
    g_Wlo[idx] = __float2bfloat16_rn(v - __bfloat162float(h));
}

// ---------------------------------------------------------------------------
// CSR rowptr from sorted row[]
// ---------------------------------------------------------------------------
__global__ void build_rowptr(const int* __restrict__ row, int E, int Nn)
{
    const int e = blockIdx.x * blockDim.x + threadIdx.x;
    if (e >= E) return;
    const int r = row[e];
    const int prev = (e == 0) ? -1 : row[e - 1];
    for (int j = prev + 1; j <= r; j++) g_rowptr[j] = e;
    if (e == E - 1)
        for (int j = r + 1; j <= Nn; j++) g_rowptr[j] = E;
}

// ---------------------------------------------------------------------------
// Warp-MMA tile: acc += Ahi*Bhi + Alo*Bhi + Ahi*Blo, K=128 resident.
// 8 warps: warp_m = w&1 (16 rows), warp_n = w>>1 (32 cols). Warp tile 16x32.
// ---------------------------------------------------------------------------
__device__ __forceinline__ void mma_tile(float acc[4][4],
                                         uint32_t AHI, uint32_t ALO,
                                         uint32_t BHI, uint32_t BLO,
                                         int warp_m, int warp_n, int lane)
{
    const uint32_t a_off = (uint32_t)((warp_m * 16 + (lane & 15)) * LDROW + ((lane >> 4) << 3)) * 2;
    const uint32_t b_off = (uint32_t)((warp_n * 32 + (lane & 7) + ((lane >> 4) << 3)) * LDROW +
                                      (lane & 8)) * 2;
    #pragma unroll
    for (int ks = 0; ks < 8; ks++) {
        const uint32_t kb = (uint32_t)ks * 32;   // 16 bf16 = 32 B
        uint32_t aH[4], aL[4], bH[2][4], bL[2][4];
        ldm_x4(aH, AHI + a_off + kb);
        #pragma unroll
        for (int g = 0; g < 2; g++)
            ldm_x4(bH[g], BHI + b_off + kb + (uint32_t)(g * 16 * LDROW) * 2);
        #pragma unroll
        for (int g = 0; g < 2; g++) {
            mma16816(acc[2 * g],     aH, bH[g]);
            mma16816(acc[2 * g + 1], aH, bH[g] + 2);
        }
        ldm_x4(aL, ALO + a_off + kb);
        #pragma unroll
        for (int g = 0; g < 2; g++) {
            mma16816(acc[2 * g],     aL, bH[g]);
            mma16816(acc[2 * g + 1], aL, bH[g] + 2);
        }
        #pragma unroll
        for (int g = 0; g < 2; g++)
            ldm_x4(bL[g], BLO + b_off + kb + (uint32_t)(g * 16 * LDROW) * 2);
        #pragma unroll
        for (int g = 0; g < 2; g++) {
            mma16816(acc[2 * g],     aH, bL[g]);
            mma16816(acc[2 * g + 1], aH, bL[g] + 2);
        }
    }
}

__device__ __forceinline__ void load_B_async(uint32_t sbase, uint32_t bhi_e, uint32_t blo_e,
                                             int tid,
                                             const __nv_bfloat16* Bhi, const __nv_bfloat16* Blo)
{
    #pragma unroll
    for (int c = 0; c < 2048; c += 256) {
        const int cc = c + tid;
        const int r = cc >> 4, col = (cc & 15) * 8;
        cp16(sbase + (bhi_e + (uint32_t)(r * LDROW + col)) * 2, Bhi + r * 128 + col);
        cp16(sbase + (blo_e + (uint32_t)(r * LDROW + col)) * 2, Blo + r * 128 + col);
    }
}

// ---------------------------------------------------------------------------
// Persistent QKV projection: loads fp32 x directly (register prefetch),
// converts to hi/lo smem in-register. grid=(99,3). Head-major outputs; Q*0.5.
// K -> g_KV[...][0..127], V -> g_KV[...][128..255].
// ---------------------------------------------------------------------------
__global__ __launch_bounds__(256, 2) void qkv_tc(
    const float* __restrict__ x,
    const float* __restrict__ bq, const float* __restrict__ bk,
    const float* __restrict__ bv, int Nn, int ntiles)
{
    extern __shared__ __nv_bfloat16 sm[];
    const uint32_t sbase = smem_u32(sm);
    const int tid = threadIdx.x;
    const int lane = tid & 31;
    const int w = tid >> 5;
    const int warp_m = w & 1;
    const int warp_n = w >> 1;
    const int o = blockIdx.y;

    // destination: Q is its own array (stride 128); K/V interleave into g_KV (stride 256)
    float* dst;
    size_t dstride;
    if (o == 0) { dst = g_Q; dstride = 128; }
    else if (o == 1) { dst = g_KV; dstride = 256; }
    else { dst = g_KV + 128; dstride = 256; }
    const float alpha = (o == 0) ? 0.5f : 1.0f;
    const float* bias = (o == 0) ? bq : (o == 1) ? bk : bv;

    // hoisted epilogue constants (fixed per thread)
    int p0c[4], p1c[4];
    float b0c[4], b1c[4];
    #pragma unroll
    for (int nb = 0; nb < 4; nb++) {
        const int f0 = warp_n * 32 + nb * 8 + (lane & 3) * 2;
        const int f1 = f0 + 1;
        p0c[nb] = (f0 & 3) * 32 + (f0 >> 2);
        p1c[nb] = (f1 & 3) * 32 + (f1 >> 2);
        b0c[nb] = __ldg(&bias[f0]);
        b1c[nb] = __ldg(&bias[f1]);
    }

    load_B_async(sbase, QKV_B_HI, QKV_B_LO, tid, g_Whi + o * 16384, g_Wlo + o * 16384);
    CP_COMMIT();

    // A-loader mapping: 8 threads per row, 16 floats each
    const int arow = tid >> 3;
    const int acol = (tid & 7) * 16;

    int t = blockIdx.x;
    float4 r[4];
    if (t < ntiles) {
        const int m = t * A_ROWS + arow;
        const float* src = x + (size_t)m * 128 + acol;
        const bool v = m < Nn;
        #pragma unroll
        for (int i = 0; i < 4; i++)
            r[i] = v ? *(const float4*)(src + i * 4) : make_float4(0.f, 0.f, 0.f, 0.f);
    }
    CP_WAIT0();
    __syncthreads();   // B resident

    for (; t < ntiles; t += gridDim.x) {
        // convert prefetched regs -> A hi/lo smem
        #pragma unroll
        for (int i = 0; i < 4; i++) {
            const uint32_t e = (uint32_t)(arow * LDROW + acol + i * 4);
            split4(r[i],
                   (__nv_bfloat162*)&sm[e], (__nv_bfloat162*)&sm[e + 2],
                   (__nv_bfloat162*)&sm[QKV_A_PART + e], (__nv_bfloat162*)&sm[QKV_A_PART + e + 2]);
        }
        // prefetch next tile
        const int tn = t + gridDim.x;
        float4 rn[4];
        if (tn < ntiles) {
            const int m = tn * A_ROWS + arow;
            const float* src = x + (size_t)m * 128 + acol;
            const bool v = m < Nn;
            #pragma unroll
            for (int i = 0; i < 4; i++)
                rn[i] = v ? *(const float4*)(src + i * 4) : make_float4(0.f, 0.f, 0.f, 0.f);
        }
        __syncthreads();   // A hi/lo visible

        float acc[4][4];
        #pragma unroll
        for (int nb = 0; nb < 4; nb++)
            #pragma unroll
            for (int j = 0; j < 4; j++) acc[nb][j] = 0.f;

        mma_tile(acc, sbase, sbase + (uint32_t)QKV_A_PART * 2,
                 sbase + (uint32_t)QKV_B_HI * 2, sbase + (uint32_t)QKV_B_LO * 2,
                 warp_m, warp_n, lane);

        const int mrow = t * A_ROWS + warp_m * 16 + (lane >> 2);
        #pragma unroll
        for (int nb = 0; nb < 4; nb++) {
            if (mrow < Nn) {
                dst[(size_t)mrow * dstride + p0c[nb]] = (acc[nb][0] + b0c[nb]) * alpha;
                dst[(size_t)mrow * dstride + p1c[nb]] = (acc[nb][1] + b1c[nb]) * alpha;
            }
            if (mrow + 8 < Nn) {
                dst[(size_t)(mrow + 8) * dstride + p0c[nb]] = (acc[nb][2] + b0c[nb]) * alpha;
                dst[(size_t)(mrow + 8) * dstride + p1c[nb]] = (acc[nb][3] + b1c[nb]) * alpha;
            }
        }
        __syncthreads();   // all warps done with A before next convert
        #pragma unroll
        for (int i = 0; i < 4; i++) r[i] = rn[i];
    }
}

// ---------------------------------------------------------------------------
// Persistent output projection: A = Y hi/lo (bf16 from edge_attn), B = Wo.
// Double-buffered cp.async A tiles.
// ---------------------------------------------------------------------------
__device__ __forceinline__ void out_load_A(uint32_t sbase, int buf, int tid, int m0)
{
    const uint32_t abase = (uint32_t)(buf * OUT_A_BUF);
    #pragma unroll
    for (int c = 0; c < 512; c += 256) {
        const int cc = c + tid;
        const int r = cc >> 4, col = (cc & 15) * 8;
        cp16(sbase + (abase + (uint32_t)(r * LDROW + col)) * 2,
             g_Yhi + (size_t)(m0 + r) * 128 + col);
        cp16(sbase + (abase + (uint32_t)(OUT_A_PART + r * LDROW + col)) * 2,
             g_Ylo + (size_t)(m0 + r) * 128 + col);
    }
}

__global__ __launch_bounds__(256, 2) void out_tc(
    const float* __restrict__ bo, float* __restrict__ out, int Nn, int ntiles)
{
    extern __shared__ __nv_bfloat16 sm[];
    const uint32_t sbase = smem_u32(sm);
    const int tid = threadIdx.x;
    const int lane = tid & 31;
    const int w = tid >> 5;
    const int warp_m = w & 1;
    const int warp_n = w >> 1;

    float b0c[4], b1c[4];
    #pragma unroll
    for (int nb = 0; nb < 4; nb++) {
        const int f0 = warp_n * 32 + nb * 8 + (lane & 3) * 2;
        b0c[nb] = __ldg(&bo[f0]);
        b1c[nb] = __ldg(&bo[f0 + 1]);
    }

    load_B_async(sbase, OUT_B_HI, OUT_B_LO, tid, g_Whi + 3 * 16384, g_Wlo + 3 * 16384);
    int t = blockIdx.x;
    if (t < ntiles) out_load_A(sbase, 0, tid, t * A_ROWS);
    CP_COMMIT();

    int buf = 0;
    for (; t < ntiles; t += gridDim.x) {
        CP_WAIT0();
        __syncthreads();
        const int tn = t + gridDim.x;
        if (tn < ntiles) {
            out_load_A(sbase, buf ^ 1, tid, tn * A_ROWS);
            CP_COMMIT();
        }

        float acc[4][4];
        #pragma unroll
        for (int nb = 0; nb < 4; nb++)
            #pragma unroll
            for (int j = 0; j < 4; j++) acc[nb][j] = 0.f;

        const uint32_t AHI = sbase + (uint32_t)(buf * OUT_A_BUF) * 2;
        mma_tile(acc, AHI, AHI + (uint32_t)OUT_A_PART * 2,
                 sbase + (uint32_t)OUT_B_HI * 2, sbase + (uint32_t)OUT_B_LO * 2,
                 warp_m, warp_n, lane);

        const int mrow = t * A_ROWS + warp_m * 16 + (lane >> 2);
        #pragma unroll
        for (int nb = 0; nb < 4; nb++) {
            const int f0 = warp_n * 32 + nb * 8 + (lane & 3) * 2;
            if (mrow < Nn) {
                float2 v = make_float2(acc[nb][0] + b0c[nb], acc[nb][1] + b1c[nb]);
                *(float2*)&out[(size_t)mrow * 128 + f0] = v;
            }
            if (mrow + 8 < Nn) {
                float2 v = make_float2(acc[nb][2] + b0c[nb], acc[nb][3] + b1c[nb]);
                *(float2*)&out[(size_t)(mrow + 8) * 128 + f0] = v;
            }
        }
        buf ^= 1;
    }
}

// ---------------------------------------------------------------------------
// Fused edge attention: one warp per node, rowptr lookup, no max-subtract,
// unroll-4 direct __ldg col loads. K/V interleaved: one 1KB region per node.
// ---------------------------------------------------------------------------
__global__ __launch_bounds__(256) void edge_attn(const int* __restrict__ col, int Nn)
{
    const int i = (blockIdx.x * blockDim.x + threadIdx.x) >> 5;
    const int lane = threadIdx.x & 31;
    if (i >= Nn) return;

    const int start = g_rowptr[i];
    const int end   = g_rowptr[i + 1];

    const float4 qv = *(const float4*)&g_Q[(size_t)i * 128 + lane * 4];

    float l = 0.f;
    float4 acc = make_float4(0.f, 0.f, 0.f, 0.f);

    int e = start;
    for (; e + 4 <= end; e += 4) {
        const int c0 = __ldg(&col[e]);
        const int c1 = __ldg(&col[e + 1]);
        const int c2 = __ldg(&col[e + 2]);
        const int c3 = __ldg(&col[e + 3]);
        const float* p0 = &g_KV[(size_t)c0 * 256 + lane * 4];
        const float* p1 = &g_KV[(size_t)c1 * 256 + lane * 4];
        const float* p2 = &g_KV[(size_t)c2 * 256 + lane * 4];
        const float* p3 = &g_KV[(size_t)c3 * 256 + lane * 4];
        const float4 k0 = *(const float4*)p0;
        const float4 k1 = *(const float4*)p1;
        const float4 k2 = *(const float4*)p2;
        const float4 k3 = *(const float4*)p3;
        const float4 v0 = *(const float4*)(p0 + 128);
        const float4 v1 = *(const float4*)(p1 + 128);
        const float4 v2 = *(const float4*)(p2 + 128);
        const float4 v3 = *(const float4*)(p3 + 128);

        float s0 = qv.x * k0.x + qv.y * k0.y + qv.z * k0.z + qv.w * k0.w;
        float s1 = qv.x * k1.x + qv.y * k1.y + qv.z * k1.z + qv.w * k1.w;
        float s2 = qv.x * k2.x + qv.y * k2.y + qv.z * k2.z + qv.w * k2.w;
        float s3 = qv.x * k3.x + qv.y * k3.y + qv.z * k3.z + qv.w * k3.w;
        s0 += __shfl_xor_sync(0xffffffffu, s0, 1);
        s1 += __shfl_xor_sync(0xffffffffu, s1, 1);
        s2 += __shfl_xor_sync(0xffffffffu, s2, 1);
        s3 += __shfl_xor_sync(0xffffffffu, s3, 1);
        s0 += __shfl_xor_sync(0xffffffffu, s0, 2);
        s1 += __shfl_xor_sync(0xffffffffu, s1, 2);
        s2 += __shfl_xor_sync(0xffffffffu, s2, 2);
        s3 += __shfl_xor_sync(0xffffffffu, s3, 2);
        s0 += __shfl_xor_sync(0xffffffffu, s0, 4);
        s1 += __shfl_xor_sync(0xffffffffu, s1, 4);
        s2 += __shfl_xor_sync(0xffffffffu, s2, 4);
        s3 += __shfl_xor_sync(0xffffffffu, s3, 4);

        const float w0 = __expf(s0);
        const float w1 = __expf(s1);
        const float w2 = __expf(s2);
        const float w3 = __expf(s3);
        l += (w0 + w1) + (w2 + w3);

        acc.x += w0 * v0.x + w1 * v1.x + w2 * v2.x + w3 * v3.x;
        acc.y += w0 * v0.y + w1 * v1.y + w2 * v2.y + w3 * v3.y;
        acc.z += w0 * v0.z + w1 * v1.z + w2 * v2.z + w3 * v3.z;
        acc.w += w0 * v0.w + w1 * v1.w + w2 * v2.w + w3 * v3.w;
    }
    for (; e < end; e++) {
        const int c = __ldg(&col[e]);
        const float* p = &g_KV[(size_t)c * 256 + lane * 4];
        const float4 kv = *(const float4*)p;
        const float4 vv = *(const float4*)(p + 128);
        float s = qv.x * kv.x + qv.y * kv.y + qv.z * kv.z + qv.w * kv.w;
        s += __shfl_xor_sync(0xffffffffu, s, 1);
        s += __shfl_xor_sync(0xffffffffu, s, 2);
        s += __shfl_xor_sync(0xffffffffu, s, 4);
        const float wgt = __expf(s);
        l += wgt;
        acc.x += wgt * vv.x;
        acc.y += wgt * vv.y;
        acc.z += wgt * vv.z;
        acc.w += wgt * vv.w;
    }

    const float inv = (l > 0.f) ? (1.f / l) : 0.f;
    float4 o;
    o.x = acc.x * inv; o.y = acc.y * inv; o.z = acc.z * inv; o.w = acc.w * inv;

    __nv_bfloat162 hp0, hp1, lp0, lp1;
    split4(o, &hp0, &hp1, &lp0, &lp1);
    const size_t base = (size_t)i * 128 + lane * 4;
    *(__nv_bfloat162*)&g_Yhi[base]     = hp0;
    *(__nv_bfloat162*)&g_Yhi[base + 2] = hp1;
    *(__nv_bfloat162*)&g_Ylo[base]     = lp0;
    *(__nv_bfloat162*)&g_Ylo[base + 2] = lp1;
}

// ---------------------------------------------------------------------------
extern "C" void kernel_launch(void* const* d_in, const int* in_sizes, int n_in,
                              void* d_out, int out_size)
{
    const float* x  = (const float*)d_in[0];
    const int*   row = (const int*)d_in[1];
    const int*   col = (const int*)d_in[2];
    const float* Wq = (const float*)d_in[3];
    const float* bq = (const float*)d_in[4];
    const float* Wk = (const float*)d_in[5];
    const float* bk = (const float*)d_in[6];
    const float* Wv = (const float*)d_in[7];
    const float* bv = (const float*)d_in[8];
    const float* Wo = (const float*)d_in[9];
    const float* bo = (const float*)d_in[10];

    const int Nn = in_sizes[0] / 128;
    const int E  = in_sizes[1];
    const int ntiles = (Nn + A_ROWS - 1) / A_ROWS;

    cudaFuncSetAttribute(qkv_tc, cudaFuncAttributeMaxDynamicSharedMemorySize, QKV_SMEM_BYTES);
    cudaFuncSetAttribute(out_tc, cudaFuncAttributeMaxDynamicSharedMemorySize, OUT_SMEM_BYTES);

    convert_weights<<<256, 256>>>(Wq, Wk, Wv, Wo);
    build_rowptr<<<(E + 255) / 256, 256>>>(row, E, Nn);

    qkv_tc<<<dim3(99, 3), 256, QKV_SMEM_BYTES>>>(x, bq, bk, bv, Nn, ntiles);

    const int edge_blocks = (Nn * 32 + 255) / 256;
    edge_attn<<<edge_blocks, 256>>>(col, Nn);

    out_tc<<<dim3(296, 1), 256, OUT_SMEM_BYTES>>>(bo, (float*)d_out, Nn, ntiles);
}

// round 10
// speedup vs baseline: 1.4706x; 1.0124x over previous
#include <cuda_runtime.h>
#include <cuda_bf16.h>
#include <cstdint>

// Problem constants: N=100000, E=800000, D=128, H=4, DH=32
#define MAX_N 100096
#define MAX_E 800000
#define ND ((size_t)MAX_N * 128)

__device__ float g_Q[ND];
__device__ float g_KV[(size_t)MAX_N * 256];   // per node: K[0..127] | V[128..255]
__device__ float g_W[(size_t)MAX_E * 4];      // per edge: exp(score) for 4 heads
__device__ __nv_bfloat16 g_Yhi[ND], g_Ylo[ND];
__device__ __nv_bfloat16 g_Whi[4 * 16384], g_Wlo[4 * 16384];  // Wq,Wk,Wv,Wo(K-permuted)
__device__ int g_rowptr[MAX_N + 1];

#define LDROW 136      // bf16 elems per padded smem row (conflict-free ldmatrix)
#define A_ROWS 32

// shared GEMM smem layout (bf16 elems): A double-buffered hi/lo | B hi | B lo
#define A_PART (A_ROWS * LDROW)        // 4352
#define A_BUF  (2 * A_PART)            // 8704
#define B_HI_E (2 * A_BUF)             // 17408
#define B_LO_E (B_HI_E + 128 * LDROW)
#define SMEM_BYTES ((B_LO_E + 128 * LDROW) * 2)   // 104448

// ---------------------------------------------------------------------------
__device__ __forceinline__ uint32_t smem_u32(const void* p) {
    uint32_t a;
    asm("{ .reg .u64 t; cvta.to.shared.u64 t, %1; cvt.u32.u64 %0, t; }" : "=r"(a) : "l"(p));
    return a;
}
__device__ __forceinline__ void ldm_x4(uint32_t* r, uint32_t addr) {
    asm volatile("ldmatrix.sync.aligned.m8n8.x4.shared.b16 {%0,%1,%2,%3}, [%4];"
                 : "=r"(r[0]), "=r"(r[1]), "=r"(r[2]), "=r"(r[3]) : "r"(addr));
}
__device__ __forceinline__ void mma16816(float* d, const uint32_t* a, const uint32_t* b) {
    asm volatile(
        "mma.sync.aligned.m16n8k16.row.col.f32.bf16.bf16.f32 "
        "{%0,%1,%2,%3},{%4,%5,%6,%7},{%8,%9},{%0,%1,%2,%3};"
        : "+f"(d[0]), "+f"(d[1]), "+f"(d[2]), "+f"(d[3])
        : "r"(a[0]), "r"(a[1]), "r"(a[2]), "r"(a[3]), "r"(b[0]), "r"(b[1]));
}
__device__ __forceinline__ void cp16(uint32_t saddr, const void* gptr) {
    asm volatile("cp.async.ca.shared.global [%0], [%1], 16;" :: "r"(saddr), "l"(gptr));
}
#define CP_COMMIT() asm volatile("cp.async.commit_group;" ::: "memory")
#define CP_WAIT0()  asm volatile("cp.async.wait_group 0;" ::: "memory")

__device__ __forceinline__ void split4(float4 v, __nv_bfloat162* hi0, __nv_bfloat162* hi1,
                                       __nv_bfloat162* lo0, __nv_bfloat162* lo1) {
    __nv_bfloat16 h0 = __float2bfloat16_rn(v.x), h1 = __float2bfloat16_rn(v.y);
    __nv_bfloat16 h2 = __float2bfloat16_rn(v.z), h3 = __float2bfloat16_rn(v.w);
    hi0->x = h0; hi0->y = h1; hi1->x = h2; hi1->y = h3;
    lo0->x = __float2bfloat16_rn(v.x - __bfloat162float(h0));
    lo0->y = __float2bfloat16_rn(v.y - __bfloat162float(h1));
    lo1->x = __float2bfloat16_rn(v.z - __bfloat162float(h2));
    lo1->y = __float2bfloat16_rn(v.w - __bfloat162float(h3));
}

// ---------------------------------------------------------------------------
// Prep: weight conversion (blocks 0..255) + CSR rowptr (blocks 256..)
// ---------------------------------------------------------------------------
__global__ void prep(const float* __restrict__ Wq, const float* __restrict__ Wk,
                     const float* __restrict__ Wv, const float* __restrict__ Wo,
                     const int* __restrict__ row, int E, int Nn)
{
    const int b = blockIdx.x;
    if (b < 256) {
        const int idx = b * 256 + threadIdx.x;
        const int mat = idx >> 14, e = idx & 16383;
        const int f = e >> 7, k = e & 127;
        const float* W = (mat == 0) ? Wq : (mat == 1) ? Wk : (mat == 2) ? Wv : Wo;
        const int kk = (mat == 3) ? ((k & 31) * 4 + (k >> 5)) : k;  // undo head-major for Wo
        const float v = W[f * 128 + kk];
        __nv_bfloat16 h = __float2bfloat16_rn(v);
        g_Whi[idx] = h;
        g_Wlo[idx] = __float2bfloat16_rn(v - __bfloat162float(h));
    } else {
        const int e = (b - 256) * 256 + threadIdx.x;
        if (e >= E) return;
        const int r = row[e];
        const int prev = (e == 0) ? -1 : row[e - 1];
        for (int j = prev + 1; j <= r; j++) g_rowptr[j] = e;
        if (e == E - 1)
            for (int j = r + 1; j <= Nn; j++) g_rowptr[j] = E;
    }
}

// ---------------------------------------------------------------------------
// Warp-MMA tile: acc += Ahi*Bhi + Alo*Bhi + Ahi*Blo, K=128 resident.
// 8 warps: warp_m = w&1 (16 rows), warp_n = w>>1 (32 cols). Warp tile 16x32.
// ---------------------------------------------------------------------------
__device__ __forceinline__ void mma_tile(float acc[4][4],
                                         uint32_t AHI, uint32_t ALO,
                                         uint32_t BHI, uint32_t BLO,
                                         int warp_m, int warp_n, int lane)
{
    const uint32_t a_off = (uint32_t)((warp_m * 16 + (lane & 15)) * LDROW + ((lane >> 4) << 3)) * 2;
    const uint32_t b_off = (uint32_t)((warp_n * 32 + (lane & 7) + ((lane >> 4) << 3)) * LDROW +
                                      (lane & 8)) * 2;
    #pragma unroll
    for (int ks = 0; ks < 8; ks++) {
        const uint32_t kb = (uint32_t)ks * 32;   // 16 bf16 = 32 B
        uint32_t aH[4], aL[4], bH[2][4], bL[2][4];
        ldm_x4(aH, AHI + a_off + kb);
        #pragma unroll
        for (int g = 0; g < 2; g++)
            ldm_x4(bH[g], BHI + b_off + kb + (uint32_t)(g * 16 * LDROW) * 2);
        #pragma unroll
        for (int g = 0; g < 2; g++) {
            mma16816(acc[2 * g],     aH, bH[g]);
            mma16816(acc[2 * g + 1], aH, bH[g] + 2);
        }
        ldm_x4(aL, ALO + a_off + kb);
        #pragma unroll
        for (int g = 0; g < 2; g++) {
            mma16816(acc[2 * g],     aL, bH[g]);
            mma16816(acc[2 * g + 1], aL, bH[g] + 2);
        }
        #pragma unroll
        for (int g = 0; g < 2; g++)
            ldm_x4(bL[g], BLO + b_off + kb + (uint32_t)(g * 16 * LDROW) * 2);
        #pragma unroll
        for (int g = 0; g < 2; g++) {
            mma16816(acc[2 * g],     aH, bL[g]);
            mma16816(acc[2 * g + 1], aH, bL[g] + 2);
        }
    }
}

__device__ __forceinline__ void load_B_async(uint32_t sbase, int tid,
                                             const __nv_bfloat16* Bhi, const __nv_bfloat16* Blo)
{
    #pragma unroll
    for (int c = 0; c < 2048; c += 256) {
        const int cc = c + tid;
        const int r = cc >> 4, col = (cc & 15) * 8;
        cp16(sbase + (B_HI_E + (uint32_t)(r * LDROW + col)) * 2, Bhi + r * 128 + col);
        cp16(sbase + (B_LO_E + (uint32_t)(r * LDROW + col)) * 2, Blo + r * 128 + col);
    }
}

// ---------------------------------------------------------------------------
// Persistent QKV projection: fp32 x register-prefetched, converted into a
// DOUBLE-buffered A smem (one __syncthreads per tile). grid=(99,3).
// Head-major permuted outputs; Q*0.5. K->g_KV[..][0:128], V->g_KV[..][128:256].
// ---------------------------------------------------------------------------
__global__ __launch_bounds__(256, 2) void qkv_tc(
    const float* __restrict__ x,
    const float* __restrict__ bq, const float* __restrict__ bk,
    const float* __restrict__ bv, int Nn, int ntiles)
{
    extern __shared__ __nv_bfloat16 sm[];
    const uint32_t sbase = smem_u32(sm);
    const int tid = threadIdx.x;
    const int lane = tid & 31;
    const int w = tid >> 5;
    const int warp_m = w & 1;
    const int warp_n = w >> 1;
    const int o = blockIdx.y;

    float* dst;
    size_t dstride;
    if (o == 0) { dst = g_Q; dstride = 128; }
    else if (o == 1) { dst = g_KV; dstride = 256; }
    else { dst = g_KV + 128; dstride = 256; }
    const float alpha = (o == 0) ? 0.5f : 1.0f;
    const float* bias = (o == 0) ? bq : (o == 1) ? bk : bv;

    int p0c[4], p1c[4];
    float b0c[4], b1c[4];
    #pragma unroll
    for (int nb = 0; nb < 4; nb++) {
        const int f0 = warp_n * 32 + nb * 8 + (lane & 3) * 2;
        const int f1 = f0 + 1;
        p0c[nb] = (f0 & 3) * 32 + (f0 >> 2);
        p1c[nb] = (f1 & 3) * 32 + (f1 >> 2);
        b0c[nb] = __ldg(&bias[f0]);
        b1c[nb] = __ldg(&bias[f1]);
    }

    load_B_async(sbase, tid, g_Whi + o * 16384, g_Wlo + o * 16384);
    CP_COMMIT();

    // A-loader mapping: 8 threads per row, 16 floats each
    const int arow = tid >> 3;
    const int acol = (tid & 7) * 16;

    int t = blockIdx.x;
    float4 r[4];
    if (t < ntiles) {
        const int m = t * A_ROWS + arow;
        const float* src = x + (size_t)m * 128 + acol;
        const bool v = m < Nn;
        #pragma unroll
        for (int i = 0; i < 4; i++)
            r[i] = v ? *(const float4*)(src + i * 4) : make_float4(0.f, 0.f, 0.f, 0.f);
    }
    CP_WAIT0();
    __syncthreads();   // B resident

    int buf = 0;
    for (; t < ntiles; t += gridDim.x) {
        // convert prefetched regs -> A[buf] hi/lo smem
        const uint32_t ab = (uint32_t)(buf * A_BUF);
        #pragma unroll
        for (int i = 0; i < 4; i++) {
            const uint32_t e = ab + (uint32_t)(arow * LDROW + acol + i * 4);
            split4(r[i],
                   (__nv_bfloat162*)&sm[e], (__nv_bfloat162*)&sm[e + 2],
                   (__nv_bfloat162*)&sm[A_PART + e], (__nv_bfloat162*)&sm[A_PART + e + 2]);
        }
        // prefetch next tile
        const int tn = t + gridDim.x;
        float4 rn[4];
        if (tn < ntiles) {
            const int m = tn * A_ROWS + arow;
            const float* src = x + (size_t)m * 128 + acol;
            const bool v = m < Nn;
            #pragma unroll
            for (int i = 0; i < 4; i++)
                rn[i] = v ? *(const float4*)(src + i * 4) : make_float4(0.f, 0.f, 0.f, 0.f);
        }
        __syncthreads();   // A[buf] visible; also fences prior-tile mma reads of buf

        float acc[4][4];
        #pragma unroll
        for (int nb = 0; nb < 4; nb++)
            #pragma unroll
            for (int j = 0; j < 4; j++) acc[nb][j] = 0.f;

        const uint32_t AHI = sbase + ab * 2;
        mma_tile(acc, AHI, AHI + (uint32_t)A_PART * 2,
                 sbase + (uint32_t)B_HI_E * 2, sbase + (uint32_t)B_LO_E * 2,
                 warp_m, warp_n, lane);

        const int mrow = t * A_ROWS + warp_m * 16 + (lane >> 2);
        #pragma unroll
        for (int nb = 0; nb < 4; nb++) {
            if (mrow < Nn) {
                dst[(size_t)mrow * dstride + p0c[nb]] = (acc[nb][0] + b0c[nb]) * alpha;
                dst[(size_t)mrow * dstride + p1c[nb]] = (acc[nb][1] + b1c[nb]) * alpha;
            }
            if (mrow + 8 < Nn) {
                dst[(size_t)(mrow + 8) * dstride + p0c[nb]] = (acc[nb][2] + b0c[nb]) * alpha;
                dst[(size_t)(mrow + 8) * dstride + p1c[nb]] = (acc[nb][3] + b1c[nb]) * alpha;
            }
        }
        buf ^= 1;
        #pragma unroll
        for (int i = 0; i < 4; i++) r[i] = rn[i];
    }
}

// ---------------------------------------------------------------------------
// Persistent output projection: A = Y hi/lo, B = Wo. Double-buffered cp.async.
// ---------------------------------------------------------------------------
__device__ __forceinline__ void out_load_A(uint32_t sbase, int buf, int tid, int m0)
{
    const uint32_t abase = (uint32_t)(buf * A_BUF);
    #pragma unroll
    for (int c = 0; c < 512; c += 256) {
        const int cc = c + tid;
        const int r = cc >> 4, col = (cc & 15) * 8;
        cp16(sbase + (abase + (uint32_t)(r * LDROW + col)) * 2,
             g_Yhi + (size_t)(m0 + r) * 128 + col);
        cp16(sbase + (abase + (uint32_t)(A_PART + r * LDROW + col)) * 2,
             g_Ylo + (size_t)(m0 + r) * 128 + col);
    }
}

__global__ __launch_bounds__(256, 2) void out_tc(
    const float* __restrict__ bo, float* __restrict__ out, int Nn, int ntiles)
{
    extern __shared__ __nv_bfloat16 sm[];
    const uint32_t sbase = smem_u32(sm);
    const int tid = threadIdx.x;
    const int lane = tid & 31;
    const int w = tid >> 5;
    const int warp_m = w & 1;
    const int warp_n = w >> 1;

    float b0c[4], b1c[4];
    #pragma unroll
    for (int nb = 0; nb < 4; nb++) {
        const int f0 = warp_n * 32 + nb * 8 + (lane & 3) * 2;
        b0c[nb] = __ldg(&bo[f0]);
        b1c[nb] = __ldg(&bo[f0 + 1]);
    }

    load_B_async(sbase, tid, g_Whi + 3 * 16384, g_Wlo + 3 * 16384);
    int t = blockIdx.x;
    if (t < ntiles) out_load_A(sbase, 0, tid, t * A_ROWS);
    CP_COMMIT();

    int buf = 0;
    for (; t < ntiles; t += gridDim.x) {
        CP_WAIT0();
        __syncthreads();
        const int tn = t + gridDim.x;
        if (tn < ntiles) {
            out_load_A(sbase, buf ^ 1, tid, tn * A_ROWS);
            CP_COMMIT();
        }

        float acc[4][4];
        #pragma unroll
        for (int nb = 0; nb < 4; nb++)
            #pragma unroll
            for (int j = 0; j < 4; j++) acc[nb][j] = 0.f;

        const uint32_t AHI = sbase + (uint32_t)(buf * A_BUF) * 2;
        mma_tile(acc, AHI, AHI + (uint32_t)A_PART * 2,
                 sbase + (uint32_t)B_HI_E * 2, sbase + (uint32_t)B_LO_E * 2,
                 warp_m, warp_n, lane);

        const int mrow = t * A_ROWS + warp_m * 16 + (lane >> 2);
        #pragma unroll
        for (int nb = 0; nb < 4; nb++) {
            const int f0 = warp_n * 32 + nb * 8 + (lane & 3) * 2;
            if (mrow < Nn) {
                float2 v = make_float2(acc[nb][0] + b0c[nb], acc[nb][1] + b1c[nb]);
                *(float2*)&out[(size_t)mrow * 128 + f0] = v;
            }
            if (mrow + 8 < Nn) {
                float2 v = make_float2(acc[nb][2] + b0c[nb], acc[nb][3] + b1c[nb]);
                *(float2*)&out[(size_t)(mrow + 8) * 128 + f0] = v;
            }
        }
        buf ^= 1;
    }
}

// ---------------------------------------------------------------------------
// Edge pass 1 (scores): gather K only (51 MB working set -> L2-friendly),
// compute w = exp(q.k) per edge/head, store to g_W.
// ---------------------------------------------------------------------------
__global__ __launch_bounds__(256) void edge_score(const int* __restrict__ col, int Nn)
{
    const int i = (blockIdx.x * blockDim.x + threadIdx.x) >> 5;
    const int lane = threadIdx.x & 31;
    if (i >= Nn) return;

    const int start = g_rowptr[i];
    const int end   = g_rowptr[i + 1];

    const float4 qv = *(const float4*)&g_Q[(size_t)i * 128 + lane * 4];
    const int h = lane >> 3;

    int e = start;
    for (; e + 4 <= end; e += 4) {
        const int c0 = __ldg(&col[e]);
        const int c1 = __ldg(&col[e + 1]);
        const int c2 = __ldg(&col[e + 2]);
        const int c3 = __ldg(&col[e + 3]);
        const float4 k0 = *(const float4*)&g_KV[(size_t)c0 * 256 + lane * 4];
        const float4 k1 = *(const float4*)&g_KV[(size_t)c1 * 256 + lane * 4];
        const float4 k2 = *(const float4*)&g_KV[(size_t)c2 * 256 + lane * 4];
        const float4 k3 = *(const float4*)&g_KV[(size_t)c3 * 256 + lane * 4];

        float s0 = qv.x * k0.x + qv.y * k0.y + qv.z * k0.z + qv.w * k0.w;
        float s1 = qv.x * k1.x + qv.y * k1.y + qv.z * k1.z + qv.w * k1.w;
        float s2 = qv.x * k2.x + qv.y * k2.y + qv.z * k2.z + qv.w * k2.w;
        float s3 = qv.x * k3.x + qv.y * k3.y + qv.z * k3.z + qv.w * k3.w;
        s0 += __shfl_xor_sync(0xffffffffu, s0, 1);
        s1 += __shfl_xor_sync(0xffffffffu, s1, 1);
        s2 += __shfl_xor_sync(0xffffffffu, s2, 1);
        s3 += __shfl_xor_sync(0xffffffffu, s3, 1);
        s0 += __shfl_xor_sync(0xffffffffu, s0, 2);
        s1 += __shfl_xor_sync(0xffffffffu, s1, 2);
        s2 += __shfl_xor_sync(0xffffffffu, s2, 2);
        s3 += __shfl_xor_sync(0xffffffffu, s3, 2);
        s0 += __shfl_xor_sync(0xffffffffu, s0, 4);
        s1 += __shfl_xor_sync(0xffffffffu, s1, 4);
        s2 += __shfl_xor_sync(0xffffffffu, s2, 4);
        s3 += __shfl_xor_sync(0xffffffffu, s3, 4);

        // lanes h*8 + j (j<4) write w_j for head h -> 16 contiguous floats
        if ((lane & 4) == 0) {
            const int j = lane & 3;
            const float sj = (j == 0) ? s0 : (j == 1) ? s1 : (j == 2) ? s2 : s3;
            g_W[(size_t)(e + j) * 4 + h] = __expf(sj);
        }
    }
    for (; e < end; e++) {
        const int c = __ldg(&col[e]);
        const float4 kv = *(const float4*)&g_KV[(size_t)c * 256 + lane * 4];
        float s = qv.x * kv.x + qv.y * kv.y + qv.z * kv.z + qv.w * kv.w;
        s += __shfl_xor_sync(0xffffffffu, s, 1);
        s += __shfl_xor_sync(0xffffffffu, s, 2);
        s += __shfl_xor_sync(0xffffffffu, s, 4);
        if ((lane & 7) == 0)
            g_W[(size_t)e * 4 + h] = __expf(s);
    }
}

// ---------------------------------------------------------------------------
// Edge pass 2 (weighted sum): gather V only + weights, normalize, write Y.
// ---------------------------------------------------------------------------
__global__ __launch_bounds__(256) void edge_sum(const int* __restrict__ col, int Nn)
{
    const int i = (blockIdx.x * blockDim.x + threadIdx.x) >> 5;
    const int lane = threadIdx.x & 31;
    if (i >= Nn) return;

    const int start = g_rowptr[i];
    const int end   = g_rowptr[i + 1];
    const int h = lane >> 3;

    float l = 0.f;
    float4 acc = make_float4(0.f, 0.f, 0.f, 0.f);

    int e = start;
    for (; e + 4 <= end; e += 4) {
        const int c0 = __ldg(&col[e]);
        const int c1 = __ldg(&col[e + 1]);
        const int c2 = __ldg(&col[e + 2]);
        const int c3 = __ldg(&col[e + 3]);
        const float w0 = __ldg(&g_W[(size_t)(e + 0) * 4 + h]);
        const float w1 = __ldg(&g_W[(size_t)(e + 1) * 4 + h]);
        const float w2 = __ldg(&g_W[(size_t)(e + 2) * 4 + h]);
        const float w3 = __ldg(&g_W[(size_t)(e + 3) * 4 + h]);
        const float4 v0 = *(const float4*)&g_KV[(size_t)c0 * 256 + 128 + lane * 4];
        const float4 v1 = *(const float4*)&g_KV[(size_t)c1 * 256 + 128 + lane * 4];
        const float4 v2 = *(const float4*)&g_KV[(size_t)c2 * 256 + 128 + lane * 4];
        const float4 v3 = *(const float4*)&g_KV[(size_t)c3 * 256 + 128 + lane * 4];

        l += (w0 + w1) + (w2 + w3);
        acc.x += w0 * v0.x + w1 * v1.x + w2 * v2.x + w3 * v3.x;
        acc.y += w0 * v0.y + w1 * v1.y + w2 * v2.y + w3 * v3.y;
        acc.z += w0 * v0.z + w1 * v1.z + w2 * v2.z + w3 * v3.z;
        acc.w += w0 * v0.w + w1 * v1.w + w2 * v2.w + w3 * v3.w;
    }
    for (; e < end; e++) {
        const int c = __ldg(&col[e]);
        const float wgt = __ldg(&g_W[(size_t)e * 4 + h]);
        const float4 vv = *(const float4*)&g_KV[(size_t)c * 256 + 128 + lane * 4];
        l += wgt;
        acc.x += wgt * vv.x;
        acc.y += wgt * vv.y;
        acc.z += wgt * vv.z;
        acc.w += wgt * vv.w;
    }

    const float inv = (l > 0.f) ? (1.f / l) : 0.f;
    float4 o;
    o.x = acc.x * inv; o.y = acc.y * inv; o.z = acc.z * inv; o.w = acc.w * inv;

    __nv_bfloat162 hp0, hp1, lp0, lp1;
    split4(o, &hp0, &hp1, &lp0, &lp1);
    const size_t base = (size_t)i * 128 + lane * 4;
    *(__nv_bfloat162*)&g_Yhi[base]     = hp0;
    *(__nv_bfloat162*)&g_Yhi[base + 2] = hp1;
    *(__nv_bfloat162*)&g_Ylo[base]     = lp0;
    *(__nv_bfloat162*)&g_Ylo[base + 2] = lp1;
}

// ---------------------------------------------------------------------------
extern "C" void kernel_launch(void* const* d_in, const int* in_sizes, int n_in,
                              void* d_out, int out_size)
{
    const float* x  = (const float*)d_in[0];
    const int*   row = (const int*)d_in[1];
    const int*   col = (const int*)d_in[2];
    const float* Wq = (const float*)d_in[3];
    const float* bq = (const float*)d_in[4];
    const float* Wk = (const float*)d_in[5];
    const float* bk = (const float*)d_in[6];
    const float* Wv = (const float*)d_in[7];
    const float* bv = (const float*)d_in[8];
    const float* Wo = (const float*)d_in[9];
    const float* bo = (const float*)d_in[10];

    const int Nn = in_sizes[0] / 128;
    const int E  = in_sizes[1];
    const int ntiles = (Nn + A_ROWS - 1) / A_ROWS;

    cudaFuncSetAttribute(qkv_tc, cudaFuncAttributeMaxDynamicSharedMemorySize, SMEM_BYTES);
    cudaFuncSetAttribute(out_tc, cudaFuncAttributeMaxDynamicSharedMemorySize, SMEM_BYTES);

    prep<<<256 + (E + 255) / 256, 256>>>(Wq, Wk, Wv, Wo, row, E, Nn);

    qkv_tc<<<dim3(99, 3), 256, SMEM_BYTES>>>(x, bq, bk, bv, Nn, ntiles);

    const int edge_blocks = (Nn * 32 + 255) / 256;
    edge_score<<<edge_blocks, 256>>>(col, Nn);
    edge_sum<<<edge_blocks, 256>>>(col, Nn);

    out_tc<<<296, 256, SMEM_BYTES>>>(bo, (float*)d_out, Nn, ntiles);
}

// round 11
// speedup vs baseline: 1.5412x; 1.0480x over previous
#include <cuda_runtime.h>
#include <cuda_bf16.h>
#include <cstdint>

// Problem constants: N=100000, E=800000, D=128, H=4, DH=32
#define MAX_N 100096
#define MAX_E 800000
#define ND ((size_t)MAX_N * 128)

__device__ float g_Q[ND];
__device__ float g_KV[(size_t)MAX_N * 256];   // per node: K[0..127] | V[128..255]
__device__ float g_W[(size_t)MAX_E * 4];      // per edge: exp(score) for 4 heads
__device__ __nv_bfloat16 g_Yhi[ND], g_Ylo[ND];
__device__ __nv_bfloat16 g_Whi[4 * 16384], g_Wlo[4 * 16384];  // Wq,Wk,Wv,Wo(K-permuted)
__device__ int g_rowptr[MAX_N + 1];

#define A_ROWS 32

// ---- fused qkv smem (XOR-swizzled, rows of 256B, no padding), bytes ----
#define FA_HI 0
#define FA_LO 8192
#define FB(op) (16384 + (op) * 65536)          // hi at +0, lo at +32768
#define FUSED_SMEM_BYTES (16384 + 3 * 65536)   // 212992

// ---- out_tc smem (padded LDROW layout, 2 CTA/SM), bf16 elems ----
#define LDROW 136
#define A_PART (A_ROWS * LDROW)        // 4352
#define A_BUF  (2 * A_PART)            // 8704
#define B_HI_E (2 * A_BUF)             // 17408
#define B_LO_E (B_HI_E + 128 * LDROW)
#define OUT_SMEM_BYTES ((B_LO_E + 128 * LDROW) * 2)   // 104448

// ---------------------------------------------------------------------------
__device__ __forceinline__ uint32_t smem_u32(const void* p) {
    uint32_t a;
    asm("{ .reg .u64 t; cvta.to.shared.u64 t, %1; cvt.u32.u64 %0, t; }" : "=r"(a) : "l"(p));
    return a;
}
__device__ __forceinline__ void ldm_x4(uint32_t* r, uint32_t addr) {
    asm volatile("ldmatrix.sync.aligned.m8n8.x4.shared.b16 {%0,%1,%2,%3}, [%4];"
                 : "=r"(r[0]), "=r"(r[1]), "=r"(r[2]), "=r"(r[3]) : "r"(addr));
}
__device__ __forceinline__ void mma16816(float* d, const uint32_t* a, const uint32_t* b) {
    asm volatile(
        "mma.sync.aligned.m16n8k16.row.col.f32.bf16.bf16.f32 "
        "{%0,%1,%2,%3},{%4,%5,%6,%7},{%8,%9},{%0,%1,%2,%3};"
        : "+f"(d[0]), "+f"(d[1]), "+f"(d[2]), "+f"(d[3])
        : "r"(a[0]), "r"(a[1]), "r"(a[2]), "r"(a[3]), "r"(b[0]), "r"(b[1]));
}
__device__ __forceinline__ void cp16(uint32_t saddr, const void* gptr) {
    asm volatile("cp.async.ca.shared.global [%0], [%1], 16;" :: "r"(saddr), "l"(gptr));
}
#define CP_COMMIT() asm volatile("cp.async.commit_group;" ::: "memory")
#define CP_WAIT0()  asm volatile("cp.async.wait_group 0;" ::: "memory")

__device__ __forceinline__ void split4(float4 v, __nv_bfloat162* hi0, __nv_bfloat162* hi1,
                                       __nv_bfloat162* lo0, __nv_bfloat162* lo1) {
    __nv_bfloat16 h0 = __float2bfloat16_rn(v.x), h1 = __float2bfloat16_rn(v.y);
    __nv_bfloat16 h2 = __float2bfloat16_rn(v.z), h3 = __float2bfloat16_rn(v.w);
    hi0->x = h0; hi0->y = h1; hi1->x = h2; hi1->y = h3;
    lo0->x = __float2bfloat16_rn(v.x - __bfloat162float(h0));
    lo0->y = __float2bfloat16_rn(v.y - __bfloat162float(h1));
    lo1->x = __float2bfloat16_rn(v.z - __bfloat162float(h2));
    lo1->y = __float2bfloat16_rn(v.w - __bfloat162float(h3));
}

// ---------------------------------------------------------------------------
// Prep: weight conversion (blocks 0..255) + CSR rowptr (blocks 256..)
// ---------------------------------------------------------------------------
__global__ void prep(const float* __restrict__ Wq, const float* __restrict__ Wk,
                     const float* __restrict__ Wv, const float* __restrict__ Wo,
                     const int* __restrict__ row, int E, int Nn)
{
    const int b = blockIdx.x;
    if (b < 256) {
        const int idx = b * 256 + threadIdx.x;
        const int mat = idx >> 14, e = idx & 16383;
        const int f = e >> 7, k = e & 127;
        const float* W = (mat == 0) ? Wq : (mat == 1) ? Wk : (mat == 2) ? Wv : Wo;
        const int kk = (mat == 3) ? ((k & 31) * 4 + (k >> 5)) : k;  // undo head-major for Wo
        const float v = W[f * 128 + kk];
        __nv_bfloat16 h = __float2bfloat16_rn(v);
        g_Whi[idx] = h;
        g_Wlo[idx] = __float2bfloat16_rn(v - __bfloat162float(h));
    } else {
        const int e = (b - 256) * 256 + threadIdx.x;
        if (e >= E) return;
        const int r = row[e];
        const int prev = (e == 0) ? -1 : row[e - 1];
        for (int j = prev + 1; j <= r; j++) g_rowptr[j] = e;
        if (e == E - 1)
            for (int j = r + 1; j <= Nn; j++) g_rowptr[j] = E;
    }
}

// ---------------------------------------------------------------------------
// Swizzled MMA tile (fused qkv): rows of 256B, chunk16 ^= (row&7).
// acc += Ahi*Bhi + Alo*Bhi + Ahi*Blo.  Warp tile 16x32.
// ---------------------------------------------------------------------------
__device__ __forceinline__ void mma_tile_sw(float acc[4][4],
                                            uint32_t AHI, uint32_t ALO,
                                            uint32_t BHI, uint32_t BLO,
                                            int warp_m, int warp_n, int lane)
{
    const int ra = warp_m * 16 + (lane & 15);
    const uint32_t a_row = (uint32_t)ra * 256;
    const uint32_t a_c0 = (uint32_t)((lane >> 4) << 4);   // 0 or 16 bytes
    const uint32_t xa = (uint32_t)((ra & 7) << 4);
    const int rb = warp_n * 32 + (lane & 7) + ((lane >> 4) << 3);
    const uint32_t b_c0 = (uint32_t)((lane & 8) * 2);     // 0 or 16 bytes
    const uint32_t xb = (uint32_t)((rb & 7) << 4);
    const uint32_t b_row0 = (uint32_t)rb * 256;

    #pragma unroll
    for (int ks = 0; ks < 8; ks++) {
        const uint32_t kb = (uint32_t)ks * 32;
        uint32_t aH[4], aL[4], bH[2][4], bL[2][4];
        ldm_x4(aH, AHI + a_row + ((a_c0 + kb) ^ xa));
        #pragma unroll
        for (int g = 0; g < 2; g++)
            ldm_x4(bH[g], BHI + b_row0 + (uint32_t)(g * 16 * 256) + ((b_c0 + kb) ^ xb));
        #pragma unroll
        for (int g = 0; g < 2; g++) {
            mma16816(acc[2 * g],     aH, bH[g]);
            mma16816(acc[2 * g + 1], aH, bH[g] + 2);
        }
        ldm_x4(aL, ALO + a_row + ((a_c0 + kb) ^ xa));
        #pragma unroll
        for (int g = 0; g < 2; g++) {
            mma16816(acc[2 * g],     aL, bH[g]);
            mma16816(acc[2 * g + 1], aL, bH[g] + 2);
        }
        #pragma unroll
        for (int g = 0; g < 2; g++)
            ldm_x4(bL[g], BLO + b_row0 + (uint32_t)(g * 16 * 256) + ((b_c0 + kb) ^ xb));
        #pragma unroll
        for (int g = 0; g < 2; g++) {
            mma16816(acc[2 * g],     aH, bL[g]);
            mma16816(acc[2 * g + 1], aH, bL[g] + 2);
        }
    }
}

// ---------------------------------------------------------------------------
// Fused persistent QKV: x read ONCE per tile; 3 resident B matrices (swizzled).
// grid = 148, 1 CTA/SM. Head-major permuted outputs; Q*0.5.
// ---------------------------------------------------------------------------
__global__ __launch_bounds__(256, 1) void qkv_fused(
    const float* __restrict__ x,
    const float* __restrict__ bq, const float* __restrict__ bk,
    const float* __restrict__ bv, int Nn, int ntiles)
{
    extern __shared__ char smb[];
    const uint32_t sbase = smem_u32(smb);
    const int tid = threadIdx.x;
    const int lane = tid & 31;
    const int w = tid >> 5;
    const int warp_m = w & 1;
    const int warp_n = w >> 1;

    // epilogue constants: permuted indices (op-independent) + per-op bias
    int p0c[4], p1c[4];
    float bb0[3][4], bb1[3][4];
    #pragma unroll
    for (int nb = 0; nb < 4; nb++) {
        const int f0 = warp_n * 32 + nb * 8 + (lane & 3) * 2;
        const int f1 = f0 + 1;
        p0c[nb] = (f0 & 3) * 32 + (f0 >> 2);
        p1c[nb] = (f1 & 3) * 32 + (f1 >> 2);
        bb0[0][nb] = __ldg(&bq[f0]); bb1[0][nb] = __ldg(&bq[f1]);
        bb0[1][nb] = __ldg(&bk[f0]); bb1[1][nb] = __ldg(&bk[f1]);
        bb0[2][nb] = __ldg(&bv[f0]); bb1[2][nb] = __ldg(&bv[f1]);
    }

    // load all 3 weight matrices hi/lo into swizzled smem
    #pragma unroll
    for (int op = 0; op < 3; op++) {
        #pragma unroll
        for (int c = 0; c < 2048; c += 256) {
            const int cc = c + tid;
            const int r = cc >> 4;
            const uint32_t cb = (uint32_t)(cc & 15) * 16;
            const uint32_t daddr = (uint32_t)r * 256 + (cb ^ (uint32_t)((r & 7) << 4));
            cp16(sbase + FB(op) + daddr,         g_Whi + op * 16384 + r * 128 + (cc & 15) * 8);
            cp16(sbase + FB(op) + 32768 + daddr, g_Wlo + op * 16384 + r * 128 + (cc & 15) * 8);
        }
    }
    CP_COMMIT();

    // A-loader mapping: 8 threads per row, 16 floats each
    const int arow = tid >> 3;
    const int acol = (tid & 7) * 16;               // elems
    const uint32_t xm = (uint32_t)((arow & 7) << 4);
    const uint32_t arow_b = (uint32_t)arow * 256;

    int t = blockIdx.x;
    float4 r[4];
    if (t < ntiles) {
        const int m = t * A_ROWS + arow;
        const float* src = x + (size_t)m * 128 + acol;
        const bool v = m < Nn;
        #pragma unroll
        for (int i = 0; i < 4; i++)
            r[i] = v ? *(const float4*)(src + i * 4) : make_float4(0.f, 0.f, 0.f, 0.f);
    }
    CP_WAIT0();
    __syncthreads();   // B resident

    for (; t < ntiles; t += gridDim.x) {
        // convert prefetched regs -> swizzled A hi/lo
        #pragma unroll
        for (int i = 0; i < 4; i++) {
            const uint32_t b = arow_b + (((uint32_t)(acol * 2 + i * 8)) ^ xm);
            split4(r[i],
                   (__nv_bfloat162*)(smb + FA_HI + b), (__nv_bfloat162*)(smb + FA_HI + b + 4),
                   (__nv_bfloat162*)(smb + FA_LO + b), (__nv_bfloat162*)(smb + FA_LO + b + 4));
        }
        // prefetch next tile
        const int tn = t + gridDim.x;
        float4 rn[4];
        if (tn < ntiles) {
            const int m = tn * A_ROWS + arow;
            const float* src = x + (size_t)m * 128 + acol;
            const bool v = m < Nn;
            #pragma unroll
            for (int i = 0; i < 4; i++)
                rn[i] = v ? *(const float4*)(src + i * 4) : make_float4(0.f, 0.f, 0.f, 0.f);
        }
        __syncthreads();   // A visible

        const int mrow = t * A_ROWS + warp_m * 16 + (lane >> 2);
        #pragma unroll
        for (int op = 0; op < 3; op++) {
            float acc[4][4];
            #pragma unroll
            for (int nb = 0; nb < 4; nb++)
                #pragma unroll
                for (int j = 0; j < 4; j++) acc[nb][j] = 0.f;

            mma_tile_sw(acc, sbase + FA_HI, sbase + FA_LO,
                        sbase + FB(op), sbase + FB(op) + 32768,
                        warp_m, warp_n, lane);

            float* dst;
            size_t dstride;
            if (op == 0) { dst = g_Q; dstride = 128; }
            else if (op == 1) { dst = g_KV; dstride = 256; }
            else { dst = g_KV + 128; dstride = 256; }
            const float alpha = (op == 0) ? 0.5f : 1.0f;

            #pragma unroll
            for (int nb = 0; nb < 4; nb++) {
                if (mrow < Nn) {
                    dst[(size_t)mrow * dstride + p0c[nb]] = (acc[nb][0] + bb0[op][nb]) * alpha;
                    dst[(size_t)mrow * dstride + p1c[nb]] = (acc[nb][1] + bb1[op][nb]) * alpha;
                }
                if (mrow + 8 < Nn) {
                    dst[(size_t)(mrow + 8) * dstride + p0c[nb]] = (acc[nb][2] + bb0[op][nb]) * alpha;
                    dst[(size_t)(mrow + 8) * dstride + p1c[nb]] = (acc[nb][3] + bb1[op][nb]) * alpha;
                }
            }
        }
        __syncthreads();   // all warps done reading A
        #pragma unroll
        for (int i = 0; i < 4; i++) r[i] = rn[i];
    }
}

// ---------------------------------------------------------------------------
// Padded-layout MMA tile (out_tc)
// ---------------------------------------------------------------------------
__device__ __forceinline__ void mma_tile(float acc[4][4],
                                         uint32_t AHI, uint32_t ALO,
                                         uint32_t BHI, uint32_t BLO,
                                         int warp_m, int warp_n, int lane)
{
    const uint32_t a_off = (uint32_t)((warp_m * 16 + (lane & 15)) * LDROW + ((lane >> 4) << 3)) * 2;
    const uint32_t b_off = (uint32_t)((warp_n * 32 + (lane & 7) + ((lane >> 4) << 3)) * LDROW +
                                      (lane & 8)) * 2;
    #pragma unroll
    for (int ks = 0; ks < 8; ks++) {
        const uint32_t kb = (uint32_t)ks * 32;
        uint32_t aH[4], aL[4], bH[2][4], bL[2][4];
        ldm_x4(aH, AHI + a_off + kb);
        #pragma unroll
        for (int g = 0; g < 2; g++)
            ldm_x4(bH[g], BHI + b_off + kb + (uint32_t)(g * 16 * LDROW) * 2);
        #pragma unroll
        for (int g = 0; g < 2; g++) {
            mma16816(acc[2 * g],     aH, bH[g]);
            mma16816(acc[2 * g + 1], aH, bH[g] + 2);
        }
        ldm_x4(aL, ALO + a_off + kb);
        #pragma unroll
        for (int g = 0; g < 2; g++) {
            mma16816(acc[2 * g],     aL, bH[g]);
            mma16816(acc[2 * g + 1], aL, bH[g] + 2);
        }
        #pragma unroll
        for (int g = 0; g < 2; g++)
            ldm_x4(bL[g], BLO + b_off + kb + (uint32_t)(g * 16 * LDROW) * 2);
        #pragma unroll
        for (int g = 0; g < 2; g++) {
            mma16816(acc[2 * g],     aH, bL[g]);
            mma16816(acc[2 * g + 1], aH, bL[g] + 2);
        }
    }
}

__device__ __forceinline__ void out_load_A(uint32_t sbase, int buf, int tid, int m0)
{
    const uint32_t abase = (uint32_t)(buf * A_BUF);
    #pragma unroll
    for (int c = 0; c < 512; c += 256) {
        const int cc = c + tid;
        const int r = cc >> 4, col = (cc & 15) * 8;
        cp16(sbase + (abase + (uint32_t)(r * LDROW + col)) * 2,
             g_Yhi + (size_t)(m0 + r) * 128 + col);
        cp16(sbase + (abase + (uint32_t)(A_PART + r * LDROW + col)) * 2,
             g_Ylo + (size_t)(m0 + r) * 128 + col);
    }
}

__global__ __launch_bounds__(256, 2) void out_tc(
    const float* __restrict__ bo, float* __restrict__ out, int Nn, int ntiles)
{
    extern __shared__ char smb[];
    const uint32_t sbase = smem_u32(smb);
    const int tid = threadIdx.x;
    const int lane = tid & 31;
    const int w = tid >> 5;
    const int warp_m = w & 1;
    const int warp_n = w >> 1;

    float b0c[4], b1c[4];
    #pragma unroll
    for (int nb = 0; nb < 4; nb++) {
        const int f0 = warp_n * 32 + nb * 8 + (lane & 3) * 2;
        b0c[nb] = __ldg(&bo[f0]);
        b1c[nb] = __ldg(&bo[f0 + 1]);
    }

    // B = Wo hi/lo into padded layout
    #pragma unroll
    for (int c = 0; c < 2048; c += 256) {
        const int cc = c + tid;
        const int r = cc >> 4, col = (cc & 15) * 8;
        cp16(sbase + (B_HI_E + (uint32_t)(r * LDROW + col)) * 2, g_Whi + 3 * 16384 + r * 128 + col);
        cp16(sbase + (B_LO_E + (uint32_t)(r * LDROW + col)) * 2, g_Wlo + 3 * 16384 + r * 128 + col);
    }
    int t = blockIdx.x;
    if (t < ntiles) out_load_A(sbase, 0, tid, t * A_ROWS);
    CP_COMMIT();

    int buf = 0;
    for (; t < ntiles; t += gridDim.x) {
        CP_WAIT0();
        __syncthreads();
        const int tn = t + gridDim.x;
        if (tn < ntiles) {
            out_load_A(sbase, buf ^ 1, tid, tn * A_ROWS);
            CP_COMMIT();
        }

        float acc[4][4];
        #pragma unroll
        for (int nb = 0; nb < 4; nb++)
            #pragma unroll
            for (int j = 0; j < 4; j++) acc[nb][j] = 0.f;

        const uint32_t AHI = sbase + (uint32_t)(buf * A_BUF) * 2;
        mma_tile(acc, AHI, AHI + (uint32_t)A_PART * 2,
                 sbase + (uint32_t)B_HI_E * 2, sbase + (uint32_t)B_LO_E * 2,
                 warp_m, warp_n, lane);

        const int mrow = t * A_ROWS + warp_m * 16 + (lane >> 2);
        #pragma unroll
        for (int nb = 0; nb < 4; nb++) {
            const int f0 = warp_n * 32 + nb * 8 + (lane & 3) * 2;
            if (mrow < Nn) {
                float2 v = make_float2(acc[nb][0] + b0c[nb], acc[nb][1] + b1c[nb]);
                *(float2*)&out[(size_t)mrow * 128 + f0] = v;
            }
            if (mrow + 8 < Nn) {
                float2 v = make_float2(acc[nb][2] + b0c[nb], acc[nb][3] + b1c[nb]);
                *(float2*)&out[(size_t)(mrow + 8) * 128 + f0] = v;
            }
        }
        buf ^= 1;
    }
}

// ---------------------------------------------------------------------------
// Edge pass 1 (scores): gather K only; w = exp(q.k) per edge/head -> g_W.
// ---------------------------------------------------------------------------
__global__ __launch_bounds__(256) void edge_score(const int* __restrict__ col, int Nn)
{
    const int i = (blockIdx.x * blockDim.x + threadIdx.x) >> 5;
    const int lane = threadIdx.x & 31;
    if (i >= Nn) return;

    const int start = g_rowptr[i];
    const int end   = g_rowptr[i + 1];

    const float4 qv = *(const float4*)&g_Q[(size_t)i * 128 + lane * 4];
    const int h = lane >> 3;

    int e = start;
    for (; e + 4 <= end; e += 4) {
        const int c0 = __ldg(&col[e]);
        const int c1 = __ldg(&col[e + 1]);
        const int c2 = __ldg(&col[e + 2]);
        const int c3 = __ldg(&col[e + 3]);
        const float4 k0 = *(const float4*)&g_KV[(size_t)c0 * 256 + lane * 4];
        const float4 k1 = *(const float4*)&g_KV[(size_t)c1 * 256 + lane * 4];
        const float4 k2 = *(const float4*)&g_KV[(size_t)c2 * 256 + lane * 4];
        const float4 k3 = *(const float4*)&g_KV[(size_t)c3 * 256 + lane * 4];

        float s0 = qv.x * k0.x + qv.y * k0.y + qv.z * k0.z + qv.w * k0.w;
        float s1 = qv.x * k1.x + qv.y * k1.y + qv.z * k1.z + qv.w * k1.w;
        float s2 = qv.x * k2.x + qv.y * k2.y + qv.z * k2.z + qv.w * k2.w;
        float s3 = qv.x * k3.x + qv.y * k3.y + qv.z * k3.z + qv.w * k3.w;
        s0 += __shfl_xor_sync(0xffffffffu, s0, 1);
        s1 += __shfl_xor_sync(0xffffffffu, s1, 1);
        s2 += __shfl_xor_sync(0xffffffffu, s2, 1);
        s3 += __shfl_xor_sync(0xffffffffu, s3, 1);
        s0 += __shfl_xor_sync(0xffffffffu, s0, 2);
        s1 += __shfl_xor_sync(0xffffffffu, s1, 2);
        s2 += __shfl_xor_sync(0xffffffffu, s2, 2);
        s3 += __shfl_xor_sync(0xffffffffu, s3, 2);
        s0 += __shfl_xor_sync(0xffffffffu, s0, 4);
        s1 += __shfl_xor_sync(0xffffffffu, s1, 4);
        s2 += __shfl_xor_sync(0xffffffffu, s2, 4);
        s3 += __shfl_xor_sync(0xffffffffu, s3, 4);

        if ((lane & 4) == 0) {
            const int j = lane & 3;
            const float sj = (j == 0) ? s0 : (j == 1) ? s1 : (j == 2) ? s2 : s3;
            g_W[(size_t)(e + j) * 4 + h] = __expf(sj);
        }
    }
    for (; e < end; e++) {
        const int c = __ldg(&col[e]);
        const float4 kv = *(const float4*)&g_KV[(size_t)c * 256 + lane * 4];
        float s = qv.x * kv.x + qv.y * kv.y + qv.z * kv.z + qv.w * kv.w;
        s += __shfl_xor_sync(0xffffffffu, s, 1);
        s += __shfl_xor_sync(0xffffffffu, s, 2);
        s += __shfl_xor_sync(0xffffffffu, s, 4);
        if ((lane & 7) == 0)
            g_W[(size_t)e * 4 + h] = __expf(s);
    }
}

// ---------------------------------------------------------------------------
// Edge pass 2 (weighted sum): gather V only + weights, normalize, write Y.
// ---------------------------------------------------------------------------
__global__ __launch_bounds__(256) void edge_sum(const int* __restrict__ col, int Nn)
{
    const int i = (blockIdx.x * blockDim.x + threadIdx.x) >> 5;
    const int lane = threadIdx.x & 31;
    if (i >= Nn) return;

    const int start = g_rowptr[i];
    const int end   = g_rowptr[i + 1];
    const int h = lane >> 3;

    float l = 0.f;
    float4 acc = make_float4(0.f, 0.f, 0.f, 0.f);

    int e = start;
    for (; e + 4 <= end; e += 4) {
        const int c0 = __ldg(&col[e]);
        const int c1 = __ldg(&col[e + 1]);
        const int c2 = __ldg(&col[e + 2]);
        const int c3 = __ldg(&col[e + 3]);
        const float w0 = __ldg(&g_W[(size_t)(e + 0) * 4 + h]);
        const float w1 = __ldg(&g_W[(size_t)(e + 1) * 4 + h]);
        const float w2 = __ldg(&g_W[(size_t)(e + 2) * 4 + h]);
        const float w3 = __ldg(&g_W[(size_t)(e + 3) * 4 + h]);
        const float4 v0 = *(const float4*)&g_KV[(size_t)c0 * 256 + 128 + lane * 4];
        const float4 v1 = *(const float4*)&g_KV[(size_t)c1 * 256 + 128 + lane * 4];
        const float4 v2 = *(const float4*)&g_KV[(size_t)c2 * 256 + 128 + lane * 4];
        const float4 v3 = *(const float4*)&g_KV[(size_t)c3 * 256 + 128 + lane * 4];

        l += (w0 + w1) + (w2 + w3);
        acc.x += w0 * v0.x + w1 * v1.x + w2 * v2.x + w3 * v3.x;
        acc.y += w0 * v0.y + w1 * v1.y + w2 * v2.y + w3 * v3.y;
        acc.z += w0 * v0.z + w1 * v1.z + w2 * v2.z + w3 * v3.z;
        acc.w += w0 * v0.w + w1 * v1.w + w2 * v2.w + w3 * v3.w;
    }
    for (; e < end; e++) {
        const int c = __ldg(&col[e]);
        const float wgt = __ldg(&g_W[(size_t)e * 4 + h]);
        const float4 vv = *(const float4*)&g_KV[(size_t)c * 256 + 128 + lane * 4];
        l += wgt;
        acc.x += wgt * vv.x;
        acc.y += wgt * vv.y;
        acc.z += wgt * vv.z;
        acc.w += wgt * vv.w;
    }

    const float inv = (l > 0.f) ? (1.f / l) : 0.f;
    float4 o;
    o.x = acc.x * inv; o.y = acc.y * inv; o.z = acc.z * inv; o.w = acc.w * inv;

    __nv_bfloat162 hp0, hp1, lp0, lp1;
    split4(o, &hp0, &hp1, &lp0, &lp1);
    const size_t base = (size_t)i * 128 + lane * 4;
    *(__nv_bfloat162*)&g_Yhi[base]     = hp0;
    *(__nv_bfloat162*)&g_Yhi[base + 2] = hp1;
    *(__nv_bfloat162*)&g_Ylo[base]     = lp0;
    *(__nv_bfloat162*)&g_Ylo[base + 2] = lp1;
}

// ---------------------------------------------------------------------------
extern "C" void kernel_launch(void* const* d_in, const int* in_sizes, int n_in,
                              void* d_out, int out_size)
{
    const float* x  = (const float*)d_in[0];
    const int*   row = (const int*)d_in[1];
    const int*   col = (const int*)d_in[2];
    const float* Wq = (const float*)d_in[3];
    const float* bq = (const float*)d_in[4];
    const float* Wk = (const float*)d_in[5];
    const float* bk = (const float*)d_in[6];
    const float* Wv = (const float*)d_in[7];
    const float* bv = (const float*)d_in[8];
    const float* Wo = (const float*)d_in[9];
    const float* bo = (const float*)d_in[10];

    const int Nn = in_sizes[0] / 128;
    const int E  = in_sizes[1];
    const int ntiles = (Nn + A_ROWS - 1) / A_ROWS;

    cudaFuncSetAttribute(qkv_fused, cudaFuncAttributeMaxDynamicSharedMemorySize, FUSED_SMEM_BYTES);
    cudaFuncSetAttribute(out_tc, cudaFuncAttributeMaxDynamicSharedMemorySize, OUT_SMEM_BYTES);

    prep<<<256 + (E + 255) / 256, 256>>>(Wq, Wk, Wv, Wo, row, E, Nn);

    qkv_fused<<<148, 256, FUSED_SMEM_BYTES>>>(x, bq, bk, bv, Nn, ntiles);

    const int edge_blocks = (Nn * 32 + 255) / 256;
    edge_score<<<edge_blocks, 256>>>(col, Nn);
    edge_sum<<<edge_blocks, 256>>>(col, Nn);

    out_tc<<<296, 256, OUT_SMEM_BYTES>>>(bo, (float*)d_out, Nn, ntiles);
}